// round 10
// baseline (speedup 1.0000x reference)
#include <cuda_runtime.h>
#include <math.h>

#define RT 4
#define N_AMB 1023
#define SLOPE 0.2f
#define NPB 8
#define NODE_BLKS 128
#define GRID 129
#define NT 512

__device__ float d_gr0[256];
__device__ float d_c0g[64];
__device__ float d_pm[GRID * 4];
__device__ float d_pz[GRID * 4];
__device__ float d_pacc[GRID * 256];
__device__ int   d_flag1, d_go, d_cnt1, d_cnt2;

__device__ __forceinline__ float leaky(float x) { return x >= 0.f ? x : SLOPE * x; }
__device__ __forceinline__ float red8(float v) {
    v += __shfl_xor_sync(0xffffffffu, v, 1);
    v += __shfl_xor_sync(0xffffffffu, v, 2);
    v += __shfl_xor_sync(0xffffffffu, v, 4);
    return v;
}
__device__ __forceinline__ float warpsum(float v) {
    #pragma unroll
    for (int off = 16; off; off >>= 1) v += __shfl_xor_sync(0xffffffffu, v, off);
    return v;
}
__device__ __forceinline__ float dot8(const float* __restrict__ w, const float* __restrict__ x) {
    const float4* w4 = (const float4*)w;
    float4 a = w4[0], b = w4[1];
    return a.x*x[0] + a.y*x[1] + a.z*x[2] + a.w*x[3]
         + b.x*x[4] + b.y*x[5] + b.z*x[6] + b.w*x[7];
}
__device__ __forceinline__ float dot16(const float* __restrict__ w, const float* __restrict__ x) {
    const float4* w4 = (const float4*)w;
    float4 a = w4[0], b = w4[1], c = w4[2], d = w4[3];
    return a.x*x[0] + a.y*x[1] + a.z*x[2] + a.w*x[3]
         + b.x*x[4] + b.y*x[5] + b.z*x[6] + b.w*x[7]
         + c.x*x[8] + c.y*x[9] + c.z*x[10] + c.w*x[11]
         + d.x*x[12] + d.y*x[13] + d.z*x[14] + d.w*x[15];
}
__device__ __forceinline__ float d44(float4 w, float4 x) {
    return w.x*x.x + w.y*x.y + w.z*x.z + w.w*x.w;
}

__global__ void __launch_bounds__(NT, 1)
mega(const float* __restrict__ hidden, const float* __restrict__ amb,
     const float* __restrict__ ta,
     const float* __restrict__ Wself,  const float* __restrict__ bself,
     const float* __restrict__ Wmerge, const float* __restrict__ bmerge,
     const float* __restrict__ Wtrans, const float* __restrict__ btrans,
     const float* __restrict__ Wl,     const float* __restrict__ Wr,
     const float* __restrict__ wattn,
     const float* __restrict__ Wd0,    const float* __restrict__ bd0,
     const float* __restrict__ Wd1,    const float* __restrict__ bd1,
     const float* __restrict__ Wd2,    const float* __restrict__ bd2,
     float* __restrict__ out) {
    __shared__ float pool[8192];     // node: al|ar then y0|y1 ; routing: Wmerge then combine
    __shared__ float s_h[512];
    __shared__ float s_p1[512];
    __shared__ float s_eall[32], s_wv[32];
    __shared__ float s_inh[64], s_avg[256], s_tmp[256], s_cat[128], s_new[64];
    __shared__ float s_M[4], s_Zi[4], s_h2[64], s_c0[64], s_e0[8];

    const int tid = threadIdx.x, lane = tid & 31, warp = tid >> 5;
    const int oid = tid >> 3, q8 = tid & 7;
    const int blk = blockIdx.x;
    const int base = blk * NPB;
    const int kb = q8 * 8;

    // ================= block 128: routing + node 0 + COMBINER =================
    if (blk == NODE_BLKS) {
        if (tid >= 256) {                 // prefetch Wmerge 32KB
            int t = tid - 256;
            float4* dst = (float4*)pool;
            const float4* src = (const float4*)Wmerge;
            #pragma unroll
            for (int i = 0; i < 8; i++) dst[t + i * 256] = src[t + i * 256];
        } else {
            if (tid < 64) s_inh[tid] = hidden[tid];
            int rt = tid >> 6, oo = tid & 63;
            s_avg[tid] = (ta[(rt * 3 + 0) * 64 + oo] + ta[(rt * 3 + 1) * 64 + oo] +
                          ta[(rt * 3 + 2) * 64 + oo]) * (1.f / 3.f);
        }
        __syncthreads();
        if (tid < 256) {
            int o4 = tid >> 2, q4 = tid & 3;
            float s = dot16(Wself + o4 * 64 + q4 * 16, &s_inh[q4 * 16]);
            s += __shfl_xor_sync(0xffffffffu, s, 1);
            s += __shfl_xor_sync(0xffffffffu, s, 2);
            if (q4 == 0) s_cat[o4] = bself[o4] + s;
            int rt = tid >> 6, oo = tid & 63;
            const float* av = &s_avg[rt * 64];
            float t = btrans[rt * 64 + oo];
            t += dot16(Wtrans + rt * 4096 + oo * 64,      av);
            t += dot16(Wtrans + rt * 4096 + oo * 64 + 16, av + 16);
            t += dot16(Wtrans + rt * 4096 + oo * 64 + 32, av + 32);
            t += dot16(Wtrans + rt * 4096 + oo * 64 + 48, av + 48);
            s_tmp[tid] = t;
        }
        __syncthreads();
        {   // serial merge chain from smem Wmerge
            float bm = bmerge[oid];
            for (int rt = 0; rt < RT; rt++) {
                if (tid < 64) s_cat[64 + tid] = s_tmp[rt * 64 + tid];
                __syncthreads();
                float m = dot16(&pool[oid * 128 + kb * 2], &s_cat[kb * 2]);
                m = red8(m);
                if (q8 == 0) s_new[oid] = leaky(bm + m);
                __syncthreads();
                if (tid < 64) s_cat[tid] = s_new[tid];
                __syncthreads();
            }
        }
        {   // gl0 -> s_h[0..255], gr0 -> s_h[256..511] + d_gr0
            int o = tid >> 1, q2 = tid & 1;
            float gl = dot16(Wl + o * 64 + q2 * 32,      &s_cat[q2 * 32])
                     + dot16(Wl + o * 64 + q2 * 32 + 16, &s_cat[q2 * 32 + 16]);
            float gr = dot16(Wr + o * 64 + q2 * 32,      &s_cat[q2 * 32])
                     + dot16(Wr + o * 64 + q2 * 32 + 16, &s_cat[q2 * 32 + 16]);
            gl += __shfl_xor_sync(0xffffffffu, gl, 1);
            gr += __shfl_xor_sync(0xffffffffu, gr, 1);
            if (q2 == 0) { s_h[o] = gl; s_h[256 + o] = gr; d_gr0[o] = gr; }
        }
        __threadfence();
        __syncthreads();
        if (tid == 0) *(volatile int*)&d_flag1 = 1;     // release g_r0
        if (warp < 8) {                   // node-0 logits e0[h]
            int h = warp >> 1, half = warp & 1, f = half * 32 + lane;
            float c = leaky(s_h[h * 64 + f] + s_h[256 + h * 64 + f]) * wattn[f];
            c = warpsum(c);
            if (lane == 0) s_e0[h * 2 + half] = c;
        }
        __syncthreads();
        if (tid < 4) { d_pm[NODE_BLKS * 4 + tid] = s_e0[tid * 2] + s_e0[tid * 2 + 1];
                       d_pz[NODE_BLKS * 4 + tid] = 1.f; }
        if (tid < 256) d_pacc[NODE_BLKS * 256 + tid] = s_h[256 + tid];
        __threadfence();
        __syncthreads();
        // ---- wait for all node partials, then combine ONCE ----
        if (tid == 0) {
            volatile int* c = &d_cnt1;
            while (*c < NODE_BLKS) __nanosleep(64);
            __threadfence();
        }
        __syncthreads();
        {
            float* s_pm    = pool;
            float* s_pz    = pool + 516;
            float* s_scale = pool + 1032;
            float* s_part  = pool + 1548;
            for (int i = tid; i < GRID * 4; i += NT) { s_pm[i] = d_pm[i]; s_pz[i] = d_pz[i]; }
            __syncthreads();
            if (warp < 4) {
                float mm = -1e30f;
                for (int b = lane; b < GRID; b += 32) mm = fmaxf(mm, s_pm[b * 4 + warp]);
                #pragma unroll
                for (int off = 16; off; off >>= 1)
                    mm = fmaxf(mm, __shfl_xor_sync(0xffffffffu, mm, off));
                if (lane == 0) s_M[warp] = mm;
            }
            __syncthreads();
            for (int i = tid; i < GRID * 4; i += NT) s_scale[i] = __expf(s_pm[i] - s_M[i & 3]);
            __syncthreads();
            if (warp < 4) {
                float zz = 0.f;
                for (int b = lane; b < GRID; b += 32) zz += s_pz[b * 4 + warp] * s_scale[b * 4 + warp];
                #pragma unroll
                for (int off = 16; off; off >>= 1) zz += __shfl_xor_sync(0xffffffffu, zz, off);
                if (lane == 0) s_Zi[warp] = 1.f / zz;
            }
            __syncthreads();
            {
                int o = tid & 255, half = tid >> 8, hh = o >> 6;
                int b0 = half ? 65 : 0, b1 = half ? GRID : 65;
                float a = 0.f;
                #pragma unroll 16
                for (int b = b0; b < b1; b++)
                    a = fmaf(d_pacc[b * 256 + o], s_scale[b * 4 + hh], a);
                s_part[half * 256 + o] = a;
            }
            __syncthreads();
            if (tid < 64) {
                float h2 = 0.f;
                #pragma unroll
                for (int hh = 0; hh < 4; hh++)
                    h2 += (s_part[hh * 64 + tid] + s_part[256 + hh * 64 + tid]) * s_Zi[hh];
                s_h2[tid] = 0.25f * h2;
            }
            __syncthreads();
            {   // c0[o] -> GLOBAL broadcast
                float p = dot8(Wd0 + oid * 128 + 64 + kb, &s_h2[kb]);
                p = red8(p);
                if (q8 == 0) d_c0g[oid] = bd0[oid] + p;
            }
        }
        __threadfence();
        __syncthreads();
        if (tid == 0) {
            *(volatile int*)&d_go = 1;
            if (atomicAdd(&d_cnt2, 1) == GRID - 1) {
                d_cnt1 = 0; d_go = 0; d_flag1 = 0;
                __threadfence();
                *(volatile int*)&d_cnt2 = 0;
            }
        }
        return;
    }

    // ===================== node blocks 0..127 =====================
    float* const s_al = pool;
    float* const s_ar = pool + 2048;
    float* const s_y0 = pool;
    float* const s_y1 = pool + 512;

    {   // amb rows base..base+7 (clamped pad) serve attention AND MLP
        int r = tid >> 6, k = tid & 63;
        int ar = base + r; if (ar >= N_AMB) ar = N_AMB - 1;
        s_h[r * 64 + k] = amb[ar * 64 + k];
    }
    __syncthreads();

    // hoist h slice into registers (reused by pass A AND MLP stage-1 dots)
    float4 hA[8], hB[8];
    #pragma unroll
    for (int r = 0; r < NPB; r++) {
        hA[r] = *(const float4*)&s_h[r * 64 + kb];
        hB[r] = *(const float4*)&s_h[r * 64 + kb + 4];
    }

    // pass A: projections -> s_al/s_ar (q8 split, h from regs)
    #pragma unroll
    for (int c = 0; c < 4; c++) {
        int o = c * 64 + oid;
        const float4* wl4 = (const float4*)(Wl + o * 64 + kb);
        const float4* wr4 = (const float4*)(Wr + o * 64 + kb);
        float4 l0 = wl4[0], l1 = wl4[1], r0 = wr4[0], r1 = wr4[1];
        #pragma unroll
        for (int r = 0; r < NPB; r++) {
            float xl = d44(l0, hA[r]) + d44(l1, hB[r]);
            float xr = d44(r0, hA[r]) + d44(r1, hB[r]);
            xl = red8(xl);
            xr = red8(xr);
            if (q8 == 0) {
                s_al[(c * 8 + r) * 64 + oid] = xl;
                s_ar[(c * 8 + r) * 64 + oid] = xr;
            }
        }
    }
    // MLP stage-1 dots, fully reduced pre-barrier (h regs, then dead)
    {
        const float4* w4 = (const float4*)(Wd0 + oid * 128 + kb);
        float4 a = w4[0], b = w4[1];
        #pragma unroll
        for (int r = 0; r < NPB; r++) {
            float s = d44(a, hA[r]) + d44(b, hB[r]);
            s = red8(s);
            if (q8 == 0) s_p1[r * 64 + oid] = s;
        }
    }
    // prefetch MLP stage-2/3 weights into regs (independent of all syncs)
    float4 w2a0, w2a1, w2b0, w2b1, w3a, w3b;
    float bb0, bb1, b3;
    const int r3 = tid >> 6, sub3 = tid & 63, o3 = sub3 >> 4, q16 = sub3 & 15;
    {
        const float4* w4 = (const float4*)(Wd1 + oid * 64 + kb);
        w2a0 = w4[0]; w2a1 = w4[1];
        const float4* w5 = (const float4*)(Wd1 + (64 + oid) * 64 + kb);
        w2b0 = w5[0]; w2b1 = w5[1];
        bb0 = bd1[oid]; bb1 = bd1[64 + oid];
        const float4* w6 = (const float4*)(Wd2 + o3 * 128 + q16 * 8);
        w3a = w6[0]; w3b = w6[1];
        b3 = bd2[o3];
    }
    if (tid == 0) {
        volatile int* f = &d_flag1;
        while (!*f) __nanosleep(32);
        __threadfence();
    }
    __syncthreads();

    // pass B: logits + per-head stats + pacc
    #pragma unroll
    for (int it = 0; it < 2; it++) {
        int task = warp * 2 + it;
        int c = task >> 3, r = task & 7;
        const float* alp = &s_al[(c * 8 + r) * 64];
        float v = leaky(alp[lane]      + d_gr0[c * 64 + lane])      * wattn[lane]
                + leaky(alp[lane + 32] + d_gr0[c * 64 + lane + 32]) * wattn[lane + 32];
        v = warpsum(v);
        if (lane == 0) s_eall[c * 8 + r] = (base + r < N_AMB) ? v : -1e30f;
    }
    __syncthreads();
    if (tid < 4) {
        int c = tid;
        float m = -1e30f;
        #pragma unroll
        for (int r = 0; r < NPB; r++) m = fmaxf(m, s_eall[c * 8 + r]);
        float z = 0.f;
        #pragma unroll
        for (int r = 0; r < NPB; r++) {
            float w = __expf(s_eall[c * 8 + r] - m);
            s_wv[c * 8 + r] = w; z += w;
        }
        d_pm[blk * 4 + c] = m;
        d_pz[blk * 4 + c] = z;
    }
    __syncthreads();
    if (tid < 256) {
        int c = tid >> 6;
        float acc = 0.f;
        #pragma unroll
        for (int r = 0; r < NPB; r++)
            acc = fmaf(s_wv[c * 8 + r], s_ar[(c * 8 + r) * 64 + (tid & 63)], acc);
        d_pacc[blk * 256 + tid] = acc;
    }
    __threadfence();
    __syncthreads();
    if (tid == 0) {
        atomicAdd(&d_cnt1, 1);
        volatile int* g = &d_go;           // combiner (block 128) releases
        while (!*g) __nanosleep(64);
        __threadfence();
    }
    __syncthreads();

    // read broadcast c0 (64 floats)
    if (tid < 64) s_c0[tid] = d_c0g[tid];
    __syncthreads();

    // MLP finish: stage 1 is now elementwise
    {
        int o = tid & 63;
        s_y0[tid] = leaky(s_c0[o] + s_p1[tid]);
    }
    __syncthreads();
    // stage 2: y0 row loaded once per r (regs), both output halves from prefetched w
    #pragma unroll
    for (int r = 0; r < NPB; r++) {
        float4 xa = *(const float4*)&s_y0[r * 64 + kb];
        float4 xb = *(const float4*)&s_y0[r * 64 + kb + 4];
        float s0 = d44(w2a0, xa) + d44(w2a1, xb);
        float s1 = d44(w2b0, xa) + d44(w2b1, xb);
        s0 = red8(s0);
        s1 = red8(s1);
        if (q8 == 0) {
            s_y1[r * 128 + oid]      = leaky(bb0 + s0);
            s_y1[r * 128 + 64 + oid] = leaky(bb1 + s1);
        }
    }
    __syncthreads();
    // stage 3 + sigmoid (prefetched w3)
    {
        float4 ya = *(const float4*)&s_y1[r3 * 128 + q16 * 8];
        float4 yb = *(const float4*)&s_y1[r3 * 128 + q16 * 8 + 4];
        float p = d44(w3a, ya) + d44(w3b, yb);
        p += __shfl_xor_sync(0xffffffffu, p, 1);
        p += __shfl_xor_sync(0xffffffffu, p, 2);
        p += __shfl_xor_sync(0xffffffffu, p, 4);
        p += __shfl_xor_sync(0xffffffffu, p, 8);
        int arr = base + r3;
        if (q16 == 0 && arr < N_AMB)
            out[arr * 4 + o3] = 1.f / (1.f + __expf(-(b3 + p)));
    }

    if (tid == 0) {
        if (atomicAdd(&d_cnt2, 1) == GRID - 1) {
            d_cnt1 = 0; d_go = 0; d_flag1 = 0;
            __threadfence();
            *(volatile int*)&d_cnt2 = 0;
        }
    }
}

extern "C" void kernel_launch(void* const* d_in, const int* in_sizes, int n_in,
                              void* d_out, int out_size) {
    const float* hidden = (const float*)d_in[0];
    const float* amb    = (const float*)d_in[1];
    const float* ta     = (const float*)d_in[2];
    const float* Wself  = (const float*)d_in[3];
    const float* bself  = (const float*)d_in[4];
    const float* Wmerge = (const float*)d_in[5];
    const float* bmerge = (const float*)d_in[6];
    const float* Wtrans = (const float*)d_in[7];
    const float* btrans = (const float*)d_in[8];
    const float* Wl     = (const float*)d_in[9];
    const float* Wr     = (const float*)d_in[10];
    const float* wattn  = (const float*)d_in[11];
    const float* Wd0    = (const float*)d_in[12];
    const float* bd0    = (const float*)d_in[13];
    const float* Wd1    = (const float*)d_in[14];
    const float* bd1    = (const float*)d_in[15];
    const float* Wd2    = (const float*)d_in[16];
    const float* bd2    = (const float*)d_in[17];
    float* out = (float*)d_out;

    mega<<<GRID, NT>>>(hidden, amb, ta, Wself, bself, Wmerge, bmerge,
                       Wtrans, btrans, Wl, Wr, wattn,
                       Wd0, bd0, Wd1, bd1, Wd2, bd2, out);
}

// round 11
// speedup vs baseline: 1.0435x; 1.0435x over previous
#include <cuda_runtime.h>
#include <math.h>

#define RT 4
#define N_AMB 1023
#define SLOPE 0.2f
#define NPB 8
#define NODE_BLKS 128
#define GRID 129
#define NT 512

__device__ float d_gr0[256];
__device__ float d_c0g[64];
__device__ float d_pm[GRID * 4];
__device__ float d_pz[GRID * 4];
__device__ float d_pacc[GRID * 256];
__device__ int   d_flag1, d_go, d_cnt1, d_cnt2;

__device__ __forceinline__ float leaky(float x) { return x >= 0.f ? x : SLOPE * x; }
__device__ __forceinline__ float red8(float v) {
    v += __shfl_xor_sync(0xffffffffu, v, 1);
    v += __shfl_xor_sync(0xffffffffu, v, 2);
    v += __shfl_xor_sync(0xffffffffu, v, 4);
    return v;
}
__device__ __forceinline__ float warpsum(float v) {
    #pragma unroll
    for (int off = 16; off; off >>= 1) v += __shfl_xor_sync(0xffffffffu, v, off);
    return v;
}
__device__ __forceinline__ float dot8(const float* __restrict__ w, const float* __restrict__ x) {
    const float4* w4 = (const float4*)w;
    float4 a = w4[0], b = w4[1];
    return a.x*x[0] + a.y*x[1] + a.z*x[2] + a.w*x[3]
         + b.x*x[4] + b.y*x[5] + b.z*x[6] + b.w*x[7];
}
__device__ __forceinline__ float dot16(const float* __restrict__ w, const float* __restrict__ x) {
    const float4* w4 = (const float4*)w;
    float4 a = w4[0], b = w4[1], c = w4[2], d = w4[3];
    return a.x*x[0] + a.y*x[1] + a.z*x[2] + a.w*x[3]
         + b.x*x[4] + b.y*x[5] + b.z*x[6] + b.w*x[7]
         + c.x*x[8] + c.y*x[9] + c.z*x[10] + c.w*x[11]
         + d.x*x[12] + d.y*x[13] + d.z*x[14] + d.w*x[15];
}
__device__ __forceinline__ float d44(float4 w, float4 x) {
    return w.x*x.x + w.y*x.y + w.z*x.z + w.w*x.w;
}
__device__ __forceinline__ void unpack2(unsigned long long v, float& x, float& y) {
    asm("mov.b64 {%0, %1}, %2;" : "=f"(x), "=f"(y) : "l"(v));
}
__device__ __forceinline__ void fma2(unsigned long long& d, unsigned long long a, unsigned long long b) {
    asm("fma.rn.f32x2 %0, %1, %2, %0;" : "+l"(d) : "l"(a), "l"(b));
}

__global__ void __launch_bounds__(NT, 1)
mega(const float* __restrict__ hidden, const float* __restrict__ amb,
     const float* __restrict__ ta,
     const float* __restrict__ Wself,  const float* __restrict__ bself,
     const float* __restrict__ Wmerge, const float* __restrict__ bmerge,
     const float* __restrict__ Wtrans, const float* __restrict__ btrans,
     const float* __restrict__ Wl,     const float* __restrict__ Wr,
     const float* __restrict__ wattn,
     const float* __restrict__ Wd0,    const float* __restrict__ bd0,
     const float* __restrict__ Wd1,    const float* __restrict__ bd1,
     const float* __restrict__ Wd2,    const float* __restrict__ bd2,
     float* __restrict__ out) {
    // pool aliasing:
    //  node pass A: s_w = pool[0..8704)  (512 cols x pad17)
    //  node later:  s_al [0..2048), s_p1 [2048..2560), s_y0 [2560..3072), s_y1 [3072..4096)
    //  routing:     Wmerge cache [0..8192), then combine scratch [0..2060)
    __shared__ float pool[8704];
    __shared__ float s_hk[64 * 12];      // h k-major, row-paired (pad 12); routing: rtmp|rcat|rnew
    __shared__ float s_h[512];           // h row-major; routing: rin|ravg then gl|gr
    __shared__ float s_eall[32], s_wv[32];
    __shared__ float s_M[4], s_Zi[4], s_h2[64], s_c0[64], s_e0[8];

    float* const s_al = pool;
    float* const s_p1 = pool + 2048;
    float* const s_y0 = pool + 2560;
    float* const s_y1 = pool + 3072;

    const int tid = threadIdx.x, lane = tid & 31, warp = tid >> 5;
    const int oid = tid >> 3, q8 = tid & 7;
    const int blk = blockIdx.x;
    const int base = blk * NPB;
    const int kb = q8 * 8;

    // ================= block 128: routing + node 0 + COMBINER =================
    if (blk == NODE_BLKS) {
        float* rin  = s_h;            // 64
        float* ravg = s_h + 64;       // 256
        float* rtmp = s_hk;           // 256
        float* rcat = s_hk + 256;     // 128
        float* rnew = s_hk + 384;     // 64
        if (tid >= 256) {             // prefetch Wmerge 32KB into pool
            int t = tid - 256;
            float4* dst = (float4*)pool;
            const float4* src = (const float4*)Wmerge;
            #pragma unroll
            for (int i = 0; i < 8; i++) dst[t + i * 256] = src[t + i * 256];
        } else {
            if (tid < 64) rin[tid] = hidden[tid];
            int rt = tid >> 6, oo = tid & 63;
            ravg[tid] = (ta[(rt * 3 + 0) * 64 + oo] + ta[(rt * 3 + 1) * 64 + oo] +
                         ta[(rt * 3 + 2) * 64 + oo]) * (1.f / 3.f);
        }
        __syncthreads();
        if (tid < 256) {
            int o4 = tid >> 2, q4 = tid & 3;
            float s = dot16(Wself + o4 * 64 + q4 * 16, &rin[q4 * 16]);
            s += __shfl_xor_sync(0xffffffffu, s, 1);
            s += __shfl_xor_sync(0xffffffffu, s, 2);
            if (q4 == 0) rcat[o4] = bself[o4] + s;
            int rt = tid >> 6, oo = tid & 63;
            const float* av = &ravg[rt * 64];
            float t = btrans[rt * 64 + oo];
            t += dot16(Wtrans + rt * 4096 + oo * 64,      av);
            t += dot16(Wtrans + rt * 4096 + oo * 64 + 16, av + 16);
            t += dot16(Wtrans + rt * 4096 + oo * 64 + 32, av + 32);
            t += dot16(Wtrans + rt * 4096 + oo * 64 + 48, av + 48);
            rtmp[tid] = t;
        }
        __syncthreads();
        {   // serial merge chain from smem Wmerge
            float bm = bmerge[oid];
            for (int rt = 0; rt < RT; rt++) {
                if (tid < 64) rcat[64 + tid] = rtmp[rt * 64 + tid];
                __syncthreads();
                float m = dot16(&pool[oid * 128 + kb * 2], &rcat[kb * 2]);
                m = red8(m);
                if (q8 == 0) rnew[oid] = leaky(bm + m);
                __syncthreads();
                if (tid < 64) rcat[tid] = rnew[tid];
                __syncthreads();
            }
        }
        {   // gl0 -> s_h[0..255], gr0 -> s_h[256..511] + d_gr0
            int o = tid >> 1, q2 = tid & 1;
            float gl = dot16(Wl + o * 64 + q2 * 32,      &rcat[q2 * 32])
                     + dot16(Wl + o * 64 + q2 * 32 + 16, &rcat[q2 * 32 + 16]);
            float gr = dot16(Wr + o * 64 + q2 * 32,      &rcat[q2 * 32])
                     + dot16(Wr + o * 64 + q2 * 32 + 16, &rcat[q2 * 32 + 16]);
            gl += __shfl_xor_sync(0xffffffffu, gl, 1);
            gr += __shfl_xor_sync(0xffffffffu, gr, 1);
            if (q2 == 0) { s_h[o] = gl; s_h[256 + o] = gr; d_gr0[o] = gr; }
        }
        __threadfence();
        __syncthreads();
        if (tid == 0) *(volatile int*)&d_flag1 = 1;     // release g_r0
        if (warp < 8) {                   // node-0 logits e0[h]
            int h = warp >> 1, half = warp & 1, f = half * 32 + lane;
            float c = leaky(s_h[h * 64 + f] + s_h[256 + h * 64 + f]) * wattn[f];
            c = warpsum(c);
            if (lane == 0) s_e0[h * 2 + half] = c;
        }
        __syncthreads();
        if (tid < 4) { d_pm[NODE_BLKS * 4 + tid] = s_e0[tid * 2] + s_e0[tid * 2 + 1];
                       d_pz[NODE_BLKS * 4 + tid] = 1.f; }
        if (tid < 256) d_pacc[NODE_BLKS * 256 + tid] = s_h[256 + tid];
        __threadfence();
        __syncthreads();
        if (tid == 0) {
            volatile int* c = &d_cnt1;
            while (*c < NODE_BLKS) __nanosleep(64);
            __threadfence();
        }
        __syncthreads();
        {   // combine ONCE (fixed order => deterministic)
            float* s_pm    = pool;
            float* s_pz    = pool + 516;
            float* s_scale = pool + 1032;
            float* s_part  = pool + 1548;
            for (int i = tid; i < GRID * 4; i += NT) { s_pm[i] = d_pm[i]; s_pz[i] = d_pz[i]; }
            __syncthreads();
            if (warp < 4) {
                float mm = -1e30f;
                for (int b = lane; b < GRID; b += 32) mm = fmaxf(mm, s_pm[b * 4 + warp]);
                #pragma unroll
                for (int off = 16; off; off >>= 1)
                    mm = fmaxf(mm, __shfl_xor_sync(0xffffffffu, mm, off));
                if (lane == 0) s_M[warp] = mm;
            }
            __syncthreads();
            for (int i = tid; i < GRID * 4; i += NT) s_scale[i] = __expf(s_pm[i] - s_M[i & 3]);
            __syncthreads();
            if (warp < 4) {
                float zz = 0.f;
                for (int b = lane; b < GRID; b += 32) zz += s_pz[b * 4 + warp] * s_scale[b * 4 + warp];
                #pragma unroll
                for (int off = 16; off; off >>= 1) zz += __shfl_xor_sync(0xffffffffu, zz, off);
                if (lane == 0) s_Zi[warp] = 1.f / zz;
            }
            __syncthreads();
            {
                int o = tid & 255, half = tid >> 8, hh = o >> 6;
                int b0 = half ? 65 : 0, b1 = half ? GRID : 65;
                float a = 0.f;
                #pragma unroll 16
                for (int b = b0; b < b1; b++)
                    a = fmaf(d_pacc[b * 256 + o], s_scale[b * 4 + hh], a);
                s_part[half * 256 + o] = a;
            }
            __syncthreads();
            if (tid < 64) {
                float h2 = 0.f;
                #pragma unroll
                for (int hh = 0; hh < 4; hh++)
                    h2 += (s_part[hh * 64 + tid] + s_part[256 + hh * 64 + tid]) * s_Zi[hh];
                s_h2[tid] = 0.25f * h2;
            }
            __syncthreads();
            {   // c0 -> global broadcast
                float p = dot8(Wd0 + oid * 128 + 64 + kb, &s_h2[kb]);
                p = red8(p);
                if (q8 == 0) d_c0g[oid] = bd0[oid] + p;
            }
        }
        __threadfence();
        __syncthreads();
        if (tid == 0) {
            *(volatile int*)&d_go = 1;
            if (atomicAdd(&d_cnt2, 1) == GRID - 1) {
                d_cnt1 = 0; d_go = 0; d_flag1 = 0;
                __threadfence();
                *(volatile int*)&d_cnt2 = 0;
            }
        }
        return;
    }

    // ===================== node blocks 0..127 =====================
    {   // h rows (clamped pad): row-major AND k-major row-paired
        int r = tid >> 6, k = tid & 63;
        int ar_ = base + r; if (ar_ >= N_AMB) ar_ = N_AMB - 1;
        float hv = amb[ar_ * 64 + k];
        s_h[r * 64 + k] = hv;
        s_hk[k * 12 + r] = hv;
    }
    __syncthreads();

    // -------- pass A: column-per-thread, k-tiled staged weights, f32x2 -------
    const int col = tid & 255;           // output column within matrix
    const int mat = tid >> 8;            // 0 = Wl, 1 = Wr
    const float* Wmat = mat ? Wr : Wl;
    unsigned long long acc[4];
    #pragma unroll
    for (int j = 0; j < 4; j++) acc[j] = 0ull;
    float* const wrow = &pool[tid * 17];
    #pragma unroll
    for (int t = 0; t < 4; t++) {
        const float4* src = (const float4*)(Wmat + col * 64 + t * 16);
        float4 c0_ = src[0], c1_ = src[1], c2_ = src[2], c3_ = src[3];
        __syncthreads();                 // prev round's smem reads done
        wrow[0]=c0_.x;  wrow[1]=c0_.y;  wrow[2]=c0_.z;  wrow[3]=c0_.w;
        wrow[4]=c1_.x;  wrow[5]=c1_.y;  wrow[6]=c1_.z;  wrow[7]=c1_.w;
        wrow[8]=c2_.x;  wrow[9]=c2_.y;  wrow[10]=c2_.z; wrow[11]=c2_.w;
        wrow[12]=c3_.x; wrow[13]=c3_.y; wrow[14]=c3_.z; wrow[15]=c3_.w;
        __syncthreads();
        #pragma unroll
        for (int kl = 0; kl < 16; kl++) {
            float w = wrow[kl];
            unsigned long long w2;
            asm("mov.b64 %0, {%1, %1};" : "=l"(w2) : "f"(w));
            int kk = t * 16 + kl;
            ulonglong2 hA = *(const ulonglong2*)&s_hk[kk * 12];
            ulonglong2 hB = *(const ulonglong2*)&s_hk[kk * 12 + 4];
            fma2(acc[0], w2, hA.x);
            fma2(acc[1], w2, hA.y);
            fma2(acc[2], w2, hB.x);
            fma2(acc[3], w2, hB.y);
        }
    }
    __syncthreads();                     // s_w dead; pool reusable
    if (mat == 0) {                      // store al (ar stays in regs)
        int c = col >> 6, f = col & 63;
        #pragma unroll
        for (int j = 0; j < 4; j++) {
            float x, y; unpack2(acc[j], x, y);
            s_al[(c * 8 + 2 * j)     * 64 + f] = x;
            s_al[(c * 8 + 2 * j + 1) * 64 + f] = y;
        }
    }
    // MLP stage-1 dots pre-barrier (overlaps cold Wd0 + flag wait)
    {
        const float4* w4 = (const float4*)(Wd0 + oid * 128 + kb);
        float4 a = w4[0], b = w4[1];
        #pragma unroll
        for (int r = 0; r < NPB; r++) {
            float4 xa = *(const float4*)&s_h[r * 64 + kb];
            float4 xb = *(const float4*)&s_h[r * 64 + kb + 4];
            float s = d44(a, xa) + d44(b, xb);
            s = red8(s);
            if (q8 == 0) s_p1[r * 64 + oid] = s;
        }
    }
    // prefetch MLP stage-2/3 weights into regs
    float4 w2a0, w2a1, w2b0, w2b1, w3a, w3b;
    float bb0, bb1, b3;
    const int r3 = tid >> 6, sub3 = tid & 63, o3 = sub3 >> 4, q16 = sub3 & 15;
    {
        const float4* w4 = (const float4*)(Wd1 + oid * 64 + kb);
        w2a0 = w4[0]; w2a1 = w4[1];
        const float4* w5 = (const float4*)(Wd1 + (64 + oid) * 64 + kb);
        w2b0 = w5[0]; w2b1 = w5[1];
        bb0 = bd1[oid]; bb1 = bd1[64 + oid];
        const float4* w6 = (const float4*)(Wd2 + o3 * 128 + q16 * 8);
        w3a = w6[0]; w3b = w6[1];
        b3 = bd2[o3];
    }
    if (tid == 0) {
        volatile int* f = &d_flag1;
        while (!*f) __nanosleep(32);
        __threadfence();
    }
    __syncthreads();

    // -------- pass B: logits + per-head stats --------
    #pragma unroll
    for (int it = 0; it < 2; it++) {
        int task = warp * 2 + it;
        int c = task >> 3, r = task & 7;
        const float* alp = &s_al[(c * 8 + r) * 64];
        float v = leaky(alp[lane]      + d_gr0[c * 64 + lane])      * wattn[lane]
                + leaky(alp[lane + 32] + d_gr0[c * 64 + lane + 32]) * wattn[lane + 32];
        v = warpsum(v);
        if (lane == 0) s_eall[c * 8 + r] = (base + r < N_AMB) ? v : -1e30f;
    }
    __syncthreads();
    if (tid < 4) {
        int c = tid;
        float m = -1e30f;
        #pragma unroll
        for (int r = 0; r < NPB; r++) m = fmaxf(m, s_eall[c * 8 + r]);
        float z = 0.f;
        #pragma unroll
        for (int r = 0; r < NPB; r++) {
            float w = __expf(s_eall[c * 8 + r] - m);
            s_wv[c * 8 + r] = w; z += w;
        }
        d_pm[blk * 4 + c] = m;
        d_pz[blk * 4 + c] = z;
    }
    __syncthreads();
    if (mat == 1) {                      // pacc straight from ar registers
        int h = col >> 6;
        float accf = 0.f;
        #pragma unroll
        for (int j = 0; j < 4; j++) {
            float x, y; unpack2(acc[j], x, y);
            accf = fmaf(s_wv[h * 8 + 2 * j],     x, accf);
            accf = fmaf(s_wv[h * 8 + 2 * j + 1], y, accf);
        }
        d_pacc[blk * 256 + col] = accf;
    }
    __threadfence();
    __syncthreads();
    if (tid == 0) {
        atomicAdd(&d_cnt1, 1);
        volatile int* g = &d_go;         // combiner releases
        while (!*g) __nanosleep(64);
        __threadfence();
    }
    __syncthreads();

    // read broadcast c0
    if (tid < 64) s_c0[tid] = d_c0g[tid];
    __syncthreads();

    // -------- MLP finish --------
    s_y0[tid] = leaky(s_c0[tid & 63] + s_p1[tid]);   // stage 1 elementwise
    __syncthreads();
    #pragma unroll
    for (int r = 0; r < NPB; r++) {      // stage 2
        float4 xa = *(const float4*)&s_y0[r * 64 + kb];
        float4 xb = *(const float4*)&s_y0[r * 64 + kb + 4];
        float s0 = d44(w2a0, xa) + d44(w2a1, xb);
        float s1 = d44(w2b0, xa) + d44(w2b1, xb);
        s0 = red8(s0);
        s1 = red8(s1);
        if (q8 == 0) {
            s_y1[r * 128 + oid]      = leaky(bb0 + s0);
            s_y1[r * 128 + 64 + oid] = leaky(bb1 + s1);
        }
    }
    __syncthreads();
    {                                    // stage 3 + sigmoid
        float4 ya = *(const float4*)&s_y1[r3 * 128 + q16 * 8];
        float4 yb = *(const float4*)&s_y1[r3 * 128 + q16 * 8 + 4];
        float p = d44(w3a, ya) + d44(w3b, yb);
        p += __shfl_xor_sync(0xffffffffu, p, 1);
        p += __shfl_xor_sync(0xffffffffu, p, 2);
        p += __shfl_xor_sync(0xffffffffu, p, 4);
        p += __shfl_xor_sync(0xffffffffu, p, 8);
        int arr = base + r3;
        if (q16 == 0 && arr < N_AMB)
            out[arr * 4 + o3] = 1.f / (1.f + __expf(-(b3 + p)));
    }

    if (tid == 0) {
        if (atomicAdd(&d_cnt2, 1) == GRID - 1) {
            d_cnt1 = 0; d_go = 0; d_flag1 = 0;
            __threadfence();
            *(volatile int*)&d_cnt2 = 0;
        }
    }
}

extern "C" void kernel_launch(void* const* d_in, const int* in_sizes, int n_in,
                              void* d_out, int out_size) {
    const float* hidden = (const float*)d_in[0];
    const float* amb    = (const float*)d_in[1];
    const float* ta     = (const float*)d_in[2];
    const float* Wself  = (const float*)d_in[3];
    const float* bself  = (const float*)d_in[4];
    const float* Wmerge = (const float*)d_in[5];
    const float* bmerge = (const float*)d_in[6];
    const float* Wtrans = (const float*)d_in[7];
    const float* btrans = (const float*)d_in[8];
    const float* Wl     = (const float*)d_in[9];
    const float* Wr     = (const float*)d_in[10];
    const float* wattn  = (const float*)d_in[11];
    const float* Wd0    = (const float*)d_in[12];
    const float* bd0    = (const float*)d_in[13];
    const float* Wd1    = (const float*)d_in[14];
    const float* bd1    = (const float*)d_in[15];
    const float* Wd2    = (const float*)d_in[16];
    const float* bd2    = (const float*)d_in[17];
    float* out = (float*)d_out;

    mega<<<GRID, NT>>>(hidden, amb, ta, Wself, bself, Wmerge, bmerge,
                       Wtrans, btrans, Wl, Wr, wattn,
                       Wd0, bd0, Wd1, bd1, Wd2, bd2, out);
}

// round 12
// speedup vs baseline: 1.0626x; 1.0184x over previous
#include <cuda_runtime.h>
#include <math.h>

#define RT 4
#define N_AMB 1023
#define SLOPE 0.2f
#define NPB 8
#define NODE_BLKS 128
#define GRID 129
#define NT 512

__device__ float d_gr0[256];
__device__ float d_c0g[64];
__device__ float d_pm[GRID * 4];
__device__ float d_pz[GRID * 4];
__device__ float d_pacc[GRID * 256];
__device__ int   d_flag1, d_go, d_cnt1, d_cnt2;

__device__ __forceinline__ float leaky(float x) { return x >= 0.f ? x : SLOPE * x; }
__device__ __forceinline__ float red8(float v) {
    v += __shfl_xor_sync(0xffffffffu, v, 1);
    v += __shfl_xor_sync(0xffffffffu, v, 2);
    v += __shfl_xor_sync(0xffffffffu, v, 4);
    return v;
}
__device__ __forceinline__ float warpsum(float v) {
    #pragma unroll
    for (int off = 16; off; off >>= 1) v += __shfl_xor_sync(0xffffffffu, v, off);
    return v;
}
__device__ __forceinline__ float dot8(const float* __restrict__ w, const float* __restrict__ x) {
    const float4* w4 = (const float4*)w;
    float4 a = w4[0], b = w4[1];
    return a.x*x[0] + a.y*x[1] + a.z*x[2] + a.w*x[3]
         + b.x*x[4] + b.y*x[5] + b.z*x[6] + b.w*x[7];
}
__device__ __forceinline__ float dot16(const float* __restrict__ w, const float* __restrict__ x) {
    const float4* w4 = (const float4*)w;
    float4 a = w4[0], b = w4[1], c = w4[2], d = w4[3];
    return a.x*x[0] + a.y*x[1] + a.z*x[2] + a.w*x[3]
         + b.x*x[4] + b.y*x[5] + b.z*x[6] + b.w*x[7]
         + c.x*x[8] + c.y*x[9] + c.z*x[10] + c.w*x[11]
         + d.x*x[12] + d.y*x[13] + d.z*x[14] + d.w*x[15];
}
__device__ __forceinline__ float d44(float4 w, float4 x) {
    return w.x*x.x + w.y*x.y + w.z*x.z + w.w*x.w;
}
__device__ __forceinline__ void unpack2(unsigned long long v, float& x, float& y) {
    asm("mov.b64 {%0, %1}, %2;" : "=f"(x), "=f"(y) : "l"(v));
}
__device__ __forceinline__ void fma2(unsigned long long& d, unsigned long long a, unsigned long long b) {
    asm("fma.rn.f32x2 %0, %1, %2, %0;" : "+l"(d) : "l"(a), "l"(b));
}

__global__ void __launch_bounds__(NT, 1)
mega(const float* __restrict__ hidden, const float* __restrict__ amb,
     const float* __restrict__ ta,
     const float* __restrict__ Wself,  const float* __restrict__ bself,
     const float* __restrict__ Wmerge, const float* __restrict__ bmerge,
     const float* __restrict__ Wtrans, const float* __restrict__ btrans,
     const float* __restrict__ Wl,     const float* __restrict__ Wr,
     const float* __restrict__ wattn,
     const float* __restrict__ Wd0,    const float* __restrict__ bd0,
     const float* __restrict__ Wd1,    const float* __restrict__ bd1,
     const float* __restrict__ Wd2,    const float* __restrict__ bd2,
     float* __restrict__ out) {
    // pool: node: s_v[0..2304) s_p1[2304..2816) s_y0[2816..3328) s_y1[3328..4352)
    //       routing: Wmerge cache [0..8192), then combine scratch [0..2060)
    __shared__ __align__(16) float pool[8192];
    __shared__ __align__(16) float s_hk[768];   // h k-major row-paired pad12; routing: rtmp|bufA|bufB
    __shared__ __align__(16) float s_h[512];    // h row-major; routing: rin|ravg then gl|gr
    __shared__ float s_eall[32], s_wv[32];
    __shared__ float s_M[4], s_Zi[4], s_h2[64], s_c0[64], s_e0[8];

    float* const s_v  = pool;            // 256 cols x pad9
    float* const s_p1 = pool + 2304;
    float* const s_y0 = pool + 2816;
    float* const s_y1 = pool + 3328;

    const int tid = threadIdx.x, lane = tid & 31, warp = tid >> 5;
    const int oid = tid >> 3, q8 = tid & 7;
    const int blk = blockIdx.x;
    const int base = blk * NPB;
    const int kb = q8 * 8;

    // ================= block 128: routing + node 0 + COMBINER =================
    if (blk == NODE_BLKS) {
        float* rin  = s_h;            // 64
        float* ravg = s_h + 64;       // 256
        float* rtmp = s_hk;           // 256
        float* bufA = s_hk + 256;     // 128
        float* bufB = s_hk + 384;     // 128
        if (tid >= 256) {             // prefetch Wmerge 32KB into pool
            int t = tid - 256;
            float4* dst = (float4*)pool;
            const float4* src = (const float4*)Wmerge;
            #pragma unroll
            for (int i = 0; i < 8; i++) dst[t + i * 256] = src[t + i * 256];
        } else {
            if (tid < 64) rin[tid] = hidden[tid];
            int rt = tid >> 6, oo = tid & 63;
            ravg[tid] = (ta[(rt * 3 + 0) * 64 + oo] + ta[(rt * 3 + 1) * 64 + oo] +
                         ta[(rt * 3 + 2) * 64 + oo]) * (1.f / 3.f);
        }
        __syncthreads();
        if (tid < 256) {
            int o4 = tid >> 2, q4 = tid & 3;
            float s = dot16(Wself + o4 * 64 + q4 * 16, &rin[q4 * 16]);
            s += __shfl_xor_sync(0xffffffffu, s, 1);
            s += __shfl_xor_sync(0xffffffffu, s, 2);
            if (q4 == 0) bufA[o4] = bself[o4] + s;
            int rt = tid >> 6, oo = tid & 63;
            const float* av = &ravg[rt * 64];
            float t = btrans[rt * 64 + oo];
            t += dot16(Wtrans + rt * 4096 + oo * 64,      av);
            t += dot16(Wtrans + rt * 4096 + oo * 64 + 16, av + 16);
            t += dot16(Wtrans + rt * 4096 + oo * 64 + 32, av + 32);
            t += dot16(Wtrans + rt * 4096 + oo * 64 + 48, av + 48);
            rtmp[tid] = t;
        }
        if (tid < 64) { /* tmp0 into bufA */ }
        __syncthreads();
        if (tid < 64) bufA[64 + tid] = rtmp[tid];
        __syncthreads();
        {   // double-buffered merge chain: 1 sync per iteration
            float bm = bmerge[oid];
            float* bufs[2] = { bufA, bufB };
            #pragma unroll
            for (int rt = 0; rt < RT; rt++) {
                float* cur = bufs[rt & 1];
                float* nxt = bufs[(rt + 1) & 1];
                float m = dot16(&pool[oid * 128 + q8 * 16], &cur[q8 * 16]);
                m = red8(m);
                if (q8 == 0) nxt[oid] = leaky(bm + m);
                if (tid < 64 && rt < 3) nxt[64 + tid] = rtmp[(rt + 1) * 64 + tid];
                __syncthreads();
            }
        }
        float* rcat = ((RT & 1) ? bufB : bufA);
        {   // gl0 -> s_h[0..255], gr0 -> s_h[256..511] + d_gr0
            int o = tid >> 1, q2 = tid & 1;
            float gl = dot16(Wl + o * 64 + q2 * 32,      &rcat[q2 * 32])
                     + dot16(Wl + o * 64 + q2 * 32 + 16, &rcat[q2 * 32 + 16]);
            float gr = dot16(Wr + o * 64 + q2 * 32,      &rcat[q2 * 32])
                     + dot16(Wr + o * 64 + q2 * 32 + 16, &rcat[q2 * 32 + 16]);
            gl += __shfl_xor_sync(0xffffffffu, gl, 1);
            gr += __shfl_xor_sync(0xffffffffu, gr, 1);
            if (q2 == 0) { s_h[o] = gl; s_h[256 + o] = gr; d_gr0[o] = gr; }
        }
        __threadfence();
        __syncthreads();
        if (tid == 0) *(volatile int*)&d_flag1 = 1;     // release g_r0
        if (warp < 8) {                   // node-0 logits e0[h]
            int h = warp >> 1, half = warp & 1, f = half * 32 + lane;
            float c = leaky(s_h[h * 64 + f] + s_h[256 + h * 64 + f]) * wattn[f];
            c = warpsum(c);
            if (lane == 0) s_e0[h * 2 + half] = c;
        }
        __syncthreads();
        if (tid < 4) { d_pm[NODE_BLKS * 4 + tid] = s_e0[tid * 2] + s_e0[tid * 2 + 1];
                       d_pz[NODE_BLKS * 4 + tid] = 1.f; }
        if (tid < 256) d_pacc[NODE_BLKS * 256 + tid] = s_h[256 + tid];
        __threadfence();
        __syncthreads();
        if (tid == 0) {
            volatile int* c = &d_cnt1;
            while (*c < NODE_BLKS) __nanosleep(64);
            __threadfence();
        }
        __syncthreads();
        {   // combine ONCE (fixed order => deterministic)
            float* s_pm    = pool;
            float* s_pz    = pool + 516;
            float* s_scale = pool + 1032;
            float* s_part  = pool + 1548;
            for (int i = tid; i < GRID * 4; i += NT) { s_pm[i] = d_pm[i]; s_pz[i] = d_pz[i]; }
            __syncthreads();
            if (warp < 4) {
                float mm = -1e30f;
                for (int b = lane; b < GRID; b += 32) mm = fmaxf(mm, s_pm[b * 4 + warp]);
                #pragma unroll
                for (int off = 16; off; off >>= 1)
                    mm = fmaxf(mm, __shfl_xor_sync(0xffffffffu, mm, off));
                if (lane == 0) s_M[warp] = mm;
            }
            __syncthreads();
            for (int i = tid; i < GRID * 4; i += NT) s_scale[i] = __expf(s_pm[i] - s_M[i & 3]);
            __syncthreads();
            if (warp < 4) {
                float zz = 0.f;
                for (int b = lane; b < GRID; b += 32) zz += s_pz[b * 4 + warp] * s_scale[b * 4 + warp];
                #pragma unroll
                for (int off = 16; off; off >>= 1) zz += __shfl_xor_sync(0xffffffffu, zz, off);
                if (lane == 0) s_Zi[warp] = 1.f / zz;
            }
            __syncthreads();
            {
                int o = tid & 255, half = tid >> 8, hh = o >> 6;
                int b0 = half ? 65 : 0, b1 = half ? GRID : 65;
                float a = 0.f;
                #pragma unroll 16
                for (int b = b0; b < b1; b++)
                    a = fmaf(d_pacc[b * 256 + o], s_scale[b * 4 + hh], a);
                s_part[half * 256 + o] = a;
            }
            __syncthreads();
            if (tid < 64) {
                float h2 = 0.f;
                #pragma unroll
                for (int hh = 0; hh < 4; hh++)
                    h2 += (s_part[hh * 64 + tid] + s_part[256 + hh * 64 + tid]) * s_Zi[hh];
                s_h2[tid] = 0.25f * h2;
            }
            __syncthreads();
            {   // c0 -> global broadcast
                float p = dot8(Wd0 + oid * 128 + 64 + kb, &s_h2[kb]);
                p = red8(p);
                if (q8 == 0) d_c0g[oid] = bd0[oid] + p;
            }
        }
        __threadfence();
        __syncthreads();
        if (tid == 0) {
            *(volatile int*)&d_go = 1;
            if (atomicAdd(&d_cnt2, 1) == GRID - 1) {
                d_cnt1 = 0; d_go = 0; d_flag1 = 0;
                __threadfence();
                *(volatile int*)&d_cnt2 = 0;
            }
        }
        return;
    }

    // ===================== node blocks 0..127 =====================
    {   // h rows (clamped pad): row-major AND k-major row-paired
        int r = tid >> 6, k = tid & 63;
        int ar_ = base + r; if (ar_ >= N_AMB) ar_ = N_AMB - 1;
        float hv = amb[ar_ * 64 + k];
        s_h[r * 64 + k] = hv;
        s_hk[k * 12 + r] = hv;
    }
    __syncthreads();

    // -------- pass A: col-per-thread, weights in REGISTERS, f32x2, no syncs --
    const int col = tid & 255;
    const int mat = tid >> 8;            // 0 = Wl (-> logits), 1 = Wr (-> pacc)
    const float* Wmat = mat ? Wr : Wl;
    unsigned long long acc[4];
    #pragma unroll
    for (int j = 0; j < 4; j++) acc[j] = 0ull;
    #pragma unroll
    for (int t = 0; t < 4; t++) {
        float ws[16];
        const float4* src = (const float4*)(Wmat + col * 64 + t * 16);
        *(float4*)&ws[0]  = src[0];
        *(float4*)&ws[4]  = src[1];
        *(float4*)&ws[8]  = src[2];
        *(float4*)&ws[12] = src[3];
        #pragma unroll
        for (int kl = 0; kl < 16; kl++) {
            float w = ws[kl];
            unsigned long long w2;
            asm("mov.b64 %0, {%1, %1};" : "=l"(w2) : "f"(w));
            int kk = t * 16 + kl;
            ulonglong2 hA = *(const ulonglong2*)&s_hk[kk * 12];
            ulonglong2 hB = *(const ulonglong2*)&s_hk[kk * 12 + 4];
            fma2(acc[0], w2, hA.x);
            fma2(acc[1], w2, hA.y);
            fma2(acc[2], w2, hB.x);
            fma2(acc[3], w2, hB.y);
        }
    }
    // MLP stage-1 dots pre-barrier (overlaps cold Wd0 + flag wait)
    {
        const float4* w4 = (const float4*)(Wd0 + oid * 128 + kb);
        float4 a = w4[0], b = w4[1];
        #pragma unroll
        for (int r = 0; r < NPB; r++) {
            float4 xa = *(const float4*)&s_h[r * 64 + kb];
            float4 xb = *(const float4*)&s_h[r * 64 + kb + 4];
            float s = d44(a, xa) + d44(b, xb);
            s = red8(s);
            if (q8 == 0) s_p1[r * 64 + oid] = s;
        }
    }
    // prefetch MLP stage-2/3 weights into regs
    float4 w2a0, w2a1, w2b0, w2b1, w3a, w3b;
    float bb0, bb1, b3;
    const int r3 = tid >> 6, sub3 = tid & 63, o3 = sub3 >> 4, q16 = sub3 & 15;
    {
        const float4* w4 = (const float4*)(Wd1 + oid * 64 + kb);
        w2a0 = w4[0]; w2a1 = w4[1];
        const float4* w5 = (const float4*)(Wd1 + (64 + oid) * 64 + kb);
        w2b0 = w5[0]; w2b1 = w5[1];
        bb0 = bd1[oid]; bb1 = bd1[64 + oid];
        const float4* w6 = (const float4*)(Wd2 + o3 * 128 + q16 * 8);
        w3a = w6[0]; w3b = w6[1];
        b3 = bd2[o3];
    }
    if (tid == 0) {
        volatile int* f = &d_flag1;
        while (!*f) __nanosleep(32);
        __threadfence();
    }
    __syncthreads();

    // -------- pass B: logits from registers --------
    if (mat == 0) {
        float g0 = d_gr0[col];
        float wa = wattn[col & 63];
        #pragma unroll
        for (int j = 0; j < 4; j++) {
            float x, y; unpack2(acc[j], x, y);
            s_v[col * 9 + 2 * j]     = leaky(x + g0) * wa;
            s_v[col * 9 + 2 * j + 1] = leaky(y + g0) * wa;
        }
    }
    __syncthreads();
    {   // reduce v over 64 cols per (head,row): 16 threads each
        int hr = tid >> 4, sub = tid & 15;
        int h = hr >> 3, r = hr & 7;
        int cb = h * 64 + sub * 4;
        float s = s_v[cb * 9 + r] + s_v[(cb + 1) * 9 + r]
                + s_v[(cb + 2) * 9 + r] + s_v[(cb + 3) * 9 + r];
        s += __shfl_xor_sync(0xffffffffu, s, 1);
        s += __shfl_xor_sync(0xffffffffu, s, 2);
        s += __shfl_xor_sync(0xffffffffu, s, 4);
        s += __shfl_xor_sync(0xffffffffu, s, 8);
        if (sub == 0) s_eall[h * 8 + r] = (base + r < N_AMB) ? s : -1e30f;
    }
    __syncthreads();
    if (tid < 4) {
        int c = tid;
        float m = -1e30f;
        #pragma unroll
        for (int r = 0; r < NPB; r++) m = fmaxf(m, s_eall[c * 8 + r]);
        float z = 0.f;
        #pragma unroll
        for (int r = 0; r < NPB; r++) {
            float w = __expf(s_eall[c * 8 + r] - m);
            s_wv[c * 8 + r] = w; z += w;
        }
        d_pm[blk * 4 + c] = m;
        d_pz[blk * 4 + c] = z;
    }
    __syncthreads();
    if (mat == 1) {                      // pacc straight from ar registers
        int h = col >> 6;
        float accf = 0.f;
        #pragma unroll
        for (int j = 0; j < 4; j++) {
            float x, y; unpack2(acc[j], x, y);
            accf = fmaf(s_wv[h * 8 + 2 * j],     x, accf);
            accf = fmaf(s_wv[h * 8 + 2 * j + 1], y, accf);
        }
        d_pacc[blk * 256 + col] = accf;
    }
    __threadfence();
    __syncthreads();
    if (tid == 0) {
        atomicAdd(&d_cnt1, 1);
        volatile int* g = &d_go;         // combiner releases
        while (!*g) __nanosleep(64);
        __threadfence();
    }
    __syncthreads();

    // read broadcast c0
    if (tid < 64) s_c0[tid] = d_c0g[tid];
    __syncthreads();

    // -------- MLP finish --------
    s_y0[tid] = leaky(s_c0[tid & 63] + s_p1[tid]);   // stage 1 elementwise
    __syncthreads();
    #pragma unroll
    for (int r = 0; r < NPB; r++) {      // stage 2
        float4 xa = *(const float4*)&s_y0[r * 64 + kb];
        float4 xb = *(const float4*)&s_y0[r * 64 + kb + 4];
        float s0 = d44(w2a0, xa) + d44(w2a1, xb);
        float s1 = d44(w2b0, xa) + d44(w2b1, xb);
        s0 = red8(s0);
        s1 = red8(s1);
        if (q8 == 0) {
            s_y1[r * 128 + oid]      = leaky(bb0 + s0);
            s_y1[r * 128 + 64 + oid] = leaky(bb1 + s1);
        }
    }
    __syncthreads();
    {                                    // stage 3 + sigmoid
        float4 ya = *(const float4*)&s_y1[r3 * 128 + q16 * 8];
        float4 yb = *(const float4*)&s_y1[r3 * 128 + q16 * 8 + 4];
        float p = d44(w3a, ya) + d44(w3b, yb);
        p += __shfl_xor_sync(0xffffffffu, p, 1);
        p += __shfl_xor_sync(0xffffffffu, p, 2);
        p += __shfl_xor_sync(0xffffffffu, p, 4);
        p += __shfl_xor_sync(0xffffffffu, p, 8);
        int arr = base + r3;
        if (q16 == 0 && arr < N_AMB)
            out[arr * 4 + o3] = 1.f / (1.f + __expf(-(b3 + p)));
    }

    if (tid == 0) {
        if (atomicAdd(&d_cnt2, 1) == GRID - 1) {
            d_cnt1 = 0; d_go = 0; d_flag1 = 0;
            __threadfence();
            *(volatile int*)&d_cnt2 = 0;
        }
    }
}

extern "C" void kernel_launch(void* const* d_in, const int* in_sizes, int n_in,
                              void* d_out, int out_size) {
    const float* hidden = (const float*)d_in[0];
    const float* amb    = (const float*)d_in[1];
    const float* ta     = (const float*)d_in[2];
    const float* Wself  = (const float*)d_in[3];
    const float* bself  = (const float*)d_in[4];
    const float* Wmerge = (const float*)d_in[5];
    const float* bmerge = (const float*)d_in[6];
    const float* Wtrans = (const float*)d_in[7];
    const float* btrans = (const float*)d_in[8];
    const float* Wl     = (const float*)d_in[9];
    const float* Wr     = (const float*)d_in[10];
    const float* wattn  = (const float*)d_in[11];
    const float* Wd0    = (const float*)d_in[12];
    const float* bd0    = (const float*)d_in[13];
    const float* Wd1    = (const float*)d_in[14];
    const float* bd1    = (const float*)d_in[15];
    const float* Wd2    = (const float*)d_in[16];
    const float* bd2    = (const float*)d_in[17];
    float* out = (float*)d_out;

    mega<<<GRID, NT>>>(hidden, amb, ta, Wself, bself, Wmerge, bmerge,
                       Wtrans, btrans, Wl, Wr, wattn,
                       Wd0, bd0, Wd1, bd1, Wd2, bd2, out);
}